// round 10
// baseline (speedup 1.0000x reference)
#include <cuda_runtime.h>
#include <cuda_bf16.h>
#include <cstdint>

// ---------------------------------------------------------------------------
// FCHCGNN: 3-layer GCN, CSR gather formulation.
// Cross-layer chunked pipeline: agg_l chunks (L2-bound, main stream) overlap
// gemm_{l+1} chunks (FMA-bound, side stream). h double-buffered.
// ---------------------------------------------------------------------------

#define MAXN 100000
#define MAXE 1600000
#define CHUNKS 4

__device__ float g_h0[(size_t)MAXN * 128];    // h buffer A
__device__ float g_h1[(size_t)MAXN * 128];    // h buffer B
__device__ float g_agg[(size_t)MAXN * 128];   // aggregation buffer
__device__ float g_dis[MAXN];                 // rsqrt(deg)
__device__ int   g_cnt[MAXN];
__device__ int   g_cur[MAXN];
__device__ int   g_rowptr[MAXN + 1];
__device__ int   g_esrc[MAXE];
__device__ int   g_bsum[128];
__device__ int   g_boff[130];

// ------------------------------- degree ------------------------------------
__global__ void k_deg_init(int n) {
    int i = blockIdx.x * blockDim.x + threadIdx.x;
    if (i < n) { g_cnt[i] = 0; g_cur[i] = 0; }
}

__global__ void k_deg_count(const int* __restrict__ dst, int E) {
    int e = blockIdx.x * blockDim.x + threadIdx.x;
    if (e < E) atomicAdd(&g_cnt[dst[e]], 1);
}

__global__ void k_deg_rsqrt(int n) {
    int i = blockIdx.x * blockDim.x + threadIdx.x;
    if (i < n) g_dis[i] = rsqrtf(1.0f + (float)g_cnt[i]);
}

// ----------------------- hierarchical exclusive scan ------------------------
__global__ void k_scan_local(int n) {
    const int tid = threadIdx.x, lane = tid & 31, wid = tid >> 5;
    const int i = blockIdx.x * 1024 + tid;
    int v = (i < n) ? g_cnt[i] : 0;

    int s = v;
#pragma unroll
    for (int off = 1; off < 32; off <<= 1) {
        int t = __shfl_up_sync(0xFFFFFFFFu, s, off);
        if (lane >= off) s += t;
    }
    __shared__ int wsum[32];
    if (lane == 31) wsum[wid] = s;
    __syncthreads();
    if (wid == 0) {
        int w = wsum[lane];
#pragma unroll
        for (int off = 1; off < 32; off <<= 1) {
            int t = __shfl_up_sync(0xFFFFFFFFu, w, off);
            if (lane >= off) w += t;
        }
        wsum[lane] = w;
    }
    __syncthreads();
    int base = wid ? wsum[wid - 1] : 0;
    int incl = base + s;
    if (i < n) g_rowptr[i] = incl - v;
    if (tid == 1023) g_bsum[blockIdx.x] = incl;
}

__global__ void k_scan_bsums(int nb) {
    const int tid = threadIdx.x, lane = tid & 31, wid = tid >> 5;
    int v = (tid < nb) ? g_bsum[tid] : 0;
    int s = v;
#pragma unroll
    for (int off = 1; off < 32; off <<= 1) {
        int t = __shfl_up_sync(0xFFFFFFFFu, s, off);
        if (lane >= off) s += t;
    }
    __shared__ int wsum[4];
    if (lane == 31) wsum[wid] = s;
    __syncthreads();
    int base = 0;
    for (int w = 0; w < wid; w++) base += wsum[w];
    int incl = base + s;
    if (tid < nb) g_boff[tid] = incl - v;
    if (tid == 127) g_boff[nb] = incl;
}

__global__ void k_scan_add(int n, int nb) {
    int i = blockIdx.x * 1024 + threadIdx.x;
    if (i < n) g_rowptr[i] += g_boff[blockIdx.x];
    if (i == 0) g_rowptr[n] = g_boff[nb];
}

__global__ void k_fill(const int* __restrict__ src, const int* __restrict__ dst, int E) {
    int e = blockIdx.x * blockDim.x + threadIdx.x;
    if (e < E) {
        int d = dst[e];
        int pos = g_rowptr[d] + atomicAdd(&g_cur[d], 1);
        g_esrc[pos] = src[e];
    }
}

// ------------------------------- GEMM ---------------------------------------
// H[rows,BN] = relu?(X[rows,128]) @ W[128,BN]. 512 thr, BM=128, BK=16, TN=4.
template <int BN, int TM, bool RELU_IN>
__global__ void __launch_bounds__(512, 2)
k_gemm(const float* __restrict__ X, const float* __restrict__ W,
       float* __restrict__ H, int rowBase, int rowEnd) {
    constexpr int BM = 128, BK = 16, TN = 4, K = 128, NTH = 512;
    __shared__ float As[2][BK * BM];
    __shared__ float Bs[2][BK * BN];

    const int tid = threadIdx.x;
    const int br = rowBase + blockIdx.x * BM;
    const int tCol = tid % (BN / TN);
    const int tRow = tid / (BN / TN);

    const int aRow = tid >> 2;
    const int aSeg = tid & 3;
    constexpr int B_THREADS = BK * BN / 4;
    const bool bAct = (B_THREADS == NTH) || (tid < B_THREADS);
    const int bRow = tid / (BN / 4);
    const int bCol = (tid % (BN / 4)) * 4;
    const int gr = br + aRow;

    float acc[TM][TN];
#pragma unroll
    for (int i = 0; i < TM; i++)
#pragma unroll
        for (int j = 0; j < TN; j++) acc[i][j] = 0.0f;

    float4 aP = make_float4(0.f, 0.f, 0.f, 0.f);
    float4 bP = make_float4(0.f, 0.f, 0.f, 0.f);
    if (gr < rowEnd) aP = *(const float4*)(X + (size_t)gr * K + aSeg * 4);
    if (bAct)        bP = *(const float4*)(W + (size_t)bRow * BN + bCol);
    if (RELU_IN) {
        aP.x = fmaxf(aP.x, 0.f); aP.y = fmaxf(aP.y, 0.f);
        aP.z = fmaxf(aP.z, 0.f); aP.w = fmaxf(aP.w, 0.f);
    }
    As[0][(aSeg * 4 + 0) * BM + aRow] = aP.x;
    As[0][(aSeg * 4 + 1) * BM + aRow] = aP.y;
    As[0][(aSeg * 4 + 2) * BM + aRow] = aP.z;
    As[0][(aSeg * 4 + 3) * BM + aRow] = aP.w;
    if (bAct) *(float4*)&Bs[0][bRow * BN + bCol] = bP;
    __syncthreads();

    int buf = 0;
#pragma unroll
    for (int k0 = 0; k0 < K; k0 += BK) {
        const int nk = k0 + BK;
        if (nk < K) {
            aP = make_float4(0.f, 0.f, 0.f, 0.f);
            if (gr < rowEnd) aP = *(const float4*)(X + (size_t)gr * K + nk + aSeg * 4);
            if (bAct)        bP = *(const float4*)(W + (size_t)(nk + bRow) * BN + bCol);
            if (RELU_IN) {
                aP.x = fmaxf(aP.x, 0.f); aP.y = fmaxf(aP.y, 0.f);
                aP.z = fmaxf(aP.z, 0.f); aP.w = fmaxf(aP.w, 0.f);
            }
        }

#pragma unroll
        for (int kk = 0; kk < BK; kk++) {
            float ra[TM], rb[TN];
#pragma unroll
            for (int i = 0; i < TM / 4; i++) {
                float4 t = *(const float4*)&As[buf][kk * BM + tRow * TM + i * 4];
                ra[i * 4 + 0] = t.x; ra[i * 4 + 1] = t.y;
                ra[i * 4 + 2] = t.z; ra[i * 4 + 3] = t.w;
            }
            {
                float4 t = *(const float4*)&Bs[buf][kk * BN + tCol * TN];
                rb[0] = t.x; rb[1] = t.y; rb[2] = t.z; rb[3] = t.w;
            }
#pragma unroll
            for (int i = 0; i < TM; i++)
#pragma unroll
                for (int j = 0; j < TN; j++) acc[i][j] += ra[i] * rb[j];
        }

        if (nk < K) {
            const int nxt = buf ^ 1;
            As[nxt][(aSeg * 4 + 0) * BM + aRow] = aP.x;
            As[nxt][(aSeg * 4 + 1) * BM + aRow] = aP.y;
            As[nxt][(aSeg * 4 + 2) * BM + aRow] = aP.z;
            As[nxt][(aSeg * 4 + 3) * BM + aRow] = aP.w;
            if (bAct) *(float4*)&Bs[nxt][bRow * BN + bCol] = bP;
            __syncthreads();
            buf = nxt;
        }
    }

#pragma unroll
    for (int i = 0; i < TM; i++) {
        int grr = br + tRow * TM + i;
        if (grr < rowEnd) {
            float4 o = make_float4(acc[i][0], acc[i][1], acc[i][2], acc[i][3]);
            *(float4*)(H + (size_t)grr * BN + tCol * TN) = o;
        }
    }
}

// --------------------- gather aggregation (F=128) ---------------------------
__global__ void k_aggregate128(const float* __restrict__ h,
                               const float* __restrict__ bias,
                               int base, int cnt) {
    int w = (int)(((size_t)blockIdx.x * blockDim.x + threadIdx.x) >> 5);
    int lane = threadIdx.x & 31;
    if (w >= cnt) return;
    int node = base + w;

    const float4* __restrict__ h4 = (const float4*)h;
    float disd = g_dis[node];

    float4 acc = ((const float4*)bias)[lane];
    {
        float nrm = disd * disd;
        float4 v = h4[(size_t)node * 32 + lane];
        acc.x += v.x * nrm; acc.y += v.y * nrm;
        acc.z += v.z * nrm; acc.w += v.w * nrm;
    }

    int e = g_rowptr[node];
    int end = g_rowptr[node + 1];
    for (; e + 3 < end; e += 4) {
        int s0 = g_esrc[e],     s1 = g_esrc[e + 1];
        int s2 = g_esrc[e + 2], s3 = g_esrc[e + 3];
        float n0 = g_dis[s0] * disd, n1 = g_dis[s1] * disd;
        float n2 = g_dis[s2] * disd, n3 = g_dis[s3] * disd;
        float4 v0 = h4[(size_t)s0 * 32 + lane];
        float4 v1 = h4[(size_t)s1 * 32 + lane];
        float4 v2 = h4[(size_t)s2 * 32 + lane];
        float4 v3 = h4[(size_t)s3 * 32 + lane];
        acc.x += v0.x * n0 + v1.x * n1 + v2.x * n2 + v3.x * n3;
        acc.y += v0.y * n0 + v1.y * n1 + v2.y * n2 + v3.y * n3;
        acc.z += v0.z * n0 + v1.z * n1 + v2.z * n2 + v3.z * n3;
        acc.w += v0.w * n0 + v1.w * n1 + v2.w * n2 + v3.w * n3;
    }
    for (; e < end; e++) {
        int s0 = g_esrc[e];
        float n0 = g_dis[s0] * disd;
        float4 v0 = h4[(size_t)s0 * 32 + lane];
        acc.x += v0.x * n0; acc.y += v0.y * n0;
        acc.z += v0.z * n0; acc.w += v0.w * n0;
    }

    ((float4*)g_agg)[(size_t)node * 32 + lane] = acc;
}

// ------- gather aggregation (F=64) fused with relu + log_softmax ------------
__global__ void k_aggregate64_softmax(const float* __restrict__ h,
                                      const float* __restrict__ bias,
                                      float* __restrict__ out, int n) {
    int node = (int)(((size_t)blockIdx.x * blockDim.x + threadIdx.x) >> 5);
    int lane = threadIdx.x & 31;
    if (node >= n) return;

    const float2* __restrict__ h2 = (const float2*)h;
    float disd = g_dis[node];

    float2 acc = ((const float2*)bias)[lane];
    {
        float nrm = disd * disd;
        float2 v = h2[(size_t)node * 32 + lane];
        acc.x += v.x * nrm; acc.y += v.y * nrm;
    }

    int e = g_rowptr[node];
    int end = g_rowptr[node + 1];
    for (; e + 3 < end; e += 4) {
        int s0 = g_esrc[e],     s1 = g_esrc[e + 1];
        int s2 = g_esrc[e + 2], s3 = g_esrc[e + 3];
        float n0 = g_dis[s0] * disd, n1 = g_dis[s1] * disd;
        float n2 = g_dis[s2] * disd, n3 = g_dis[s3] * disd;
        float2 v0 = h2[(size_t)s0 * 32 + lane];
        float2 v1 = h2[(size_t)s1 * 32 + lane];
        float2 v2 = h2[(size_t)s2 * 32 + lane];
        float2 v3 = h2[(size_t)s3 * 32 + lane];
        acc.x += v0.x * n0 + v1.x * n1 + v2.x * n2 + v3.x * n3;
        acc.y += v0.y * n0 + v1.y * n1 + v2.y * n2 + v3.y * n3;
    }
    for (; e < end; e++) {
        int s0 = g_esrc[e];
        float n0 = g_dis[s0] * disd;
        float2 v0 = h2[(size_t)s0 * 32 + lane];
        acc.x += v0.x * n0; acc.y += v0.y * n0;
    }

    acc.x = fmaxf(acc.x, 0.f);
    acc.y = fmaxf(acc.y, 0.f);

    float m = fmaxf(acc.x, acc.y);
#pragma unroll
    for (int off = 16; off; off >>= 1) m = fmaxf(m, __shfl_xor_sync(0xFFFFFFFFu, m, off));

    float ssum = expf(acc.x - m) + expf(acc.y - m);
#pragma unroll
    for (int off = 16; off; off >>= 1) ssum += __shfl_xor_sync(0xFFFFFFFFu, ssum, off);

    float l = logf(ssum);
    float2 o;
    o.x = acc.x - m - l;
    o.y = acc.y - m - l;
    ((float2*)out)[(size_t)node * 32 + lane] = o;
}

// ----------------------------------------------------------------------------
extern "C" void kernel_launch(void* const* d_in, const int* in_sizes, int n_in,
                              void* d_out, int out_size) {
    const float* x  = (const float*)d_in[0];
    const int* ei   = (const int*)d_in[1];
    const float* W0 = (const float*)d_in[2];
    const float* b0 = (const float*)d_in[3];
    const float* W1 = (const float*)d_in[4];
    const float* b1 = (const float*)d_in[5];
    const float* W2 = (const float*)d_in[6];
    const float* b2 = (const float*)d_in[7];
    float* out = (float*)d_out;

    const int N = in_sizes[0] / 128;
    const int E = in_sizes[1] / 2;
    const int* src = ei;
    const int* dst = ei + E;

    const int T = 256;
    const int nb = (N + 1023) / 1024;

    // one-time setup (uncaptured correctness call): streams, events, symbol ptrs
    static cudaStream_t s_side = nullptr;
    static cudaEvent_t ev_fork = nullptr, ev_csr = nullptr;
    static cudaEvent_t ev_a0[CHUNKS], ev_a1[CHUNKS], ev_g1 = nullptr, ev_g2 = nullptr;
    static float *p_h0 = nullptr, *p_h1 = nullptr, *p_agg = nullptr;
    if (s_side == nullptr) {
        cudaStreamCreateWithFlags(&s_side, cudaStreamNonBlocking);
        cudaEventCreateWithFlags(&ev_fork, cudaEventDisableTiming);
        cudaEventCreateWithFlags(&ev_csr, cudaEventDisableTiming);
        cudaEventCreateWithFlags(&ev_g1, cudaEventDisableTiming);
        cudaEventCreateWithFlags(&ev_g2, cudaEventDisableTiming);
        for (int c = 0; c < CHUNKS; c++) {
            cudaEventCreateWithFlags(&ev_a0[c], cudaEventDisableTiming);
            cudaEventCreateWithFlags(&ev_a1[c], cudaEventDisableTiming);
        }
        cudaGetSymbolAddress((void**)&p_h0, g_h0);
        cudaGetSymbolAddress((void**)&p_h1, g_h1);
        cudaGetSymbolAddress((void**)&p_agg, g_agg);
    }

    const int chunk = (N + CHUNKS - 1) / CHUNKS;

    // ---- fork: CSR build on side stream, GEMM-0 on main stream
    cudaEventRecord(ev_fork, 0);
    cudaStreamWaitEvent(s_side, ev_fork, 0);

    k_deg_init<<<(N + T - 1) / T, T, 0, s_side>>>(N);
    k_deg_count<<<(E + T - 1) / T, T, 0, s_side>>>(dst, E);
    k_deg_rsqrt<<<(N + T - 1) / T, T, 0, s_side>>>(N);
    k_scan_local<<<nb, 1024, 0, s_side>>>(N);
    k_scan_bsums<<<1, 128, 0, s_side>>>(nb);
    k_scan_add<<<nb, 1024, 0, s_side>>>(N, nb);
    k_fill<<<(E + T - 1) / T, T, 0, s_side>>>(src, dst, E);
    cudaEventRecord(ev_csr, s_side);

    // ---- layer 0 GEMM (full), concurrent with CSR build
    k_gemm<128, 8, false><<<(N + 127) / 128, 512>>>(x, W0, p_h0, 0, N);
    cudaStreamWaitEvent(0, ev_csr, 0);   // aggregation needs CSR + dis

    // ---- boundary 0: agg0 chunks (main) || gemm1 chunks (side)
    for (int c = 0; c < CHUNKS; c++) {
        int base = c * chunk;
        int len = (base + chunk <= N) ? chunk : (N - base);
        k_aggregate128<<<(len * 32 + T - 1) / T, T>>>(p_h0, b0, base, len);
        cudaEventRecord(ev_a0[c], 0);
        cudaStreamWaitEvent(s_side, ev_a0[c], 0);
        k_gemm<128, 8, true><<<(len + 127) / 128, 512, 0, s_side>>>(
            p_agg, W1, p_h1, base, base + len);
    }
    cudaEventRecord(ev_g1, s_side);
    cudaStreamWaitEvent(0, ev_g1, 0);

    // ---- boundary 1: agg1 chunks (main) || gemm2 chunks (side)
    for (int c = 0; c < CHUNKS; c++) {
        int base = c * chunk;
        int len = (base + chunk <= N) ? chunk : (N - base);
        k_aggregate128<<<(len * 32 + T - 1) / T, T>>>(p_h1, b1, base, len);
        cudaEventRecord(ev_a1[c], 0);
        cudaStreamWaitEvent(s_side, ev_a1[c], 0);
        k_gemm<64, 4, true><<<(len + 127) / 128, 512, 0, s_side>>>(
            p_agg, W2, p_h0, base, base + len);
    }
    cudaEventRecord(ev_g2, s_side);
    cudaStreamWaitEvent(0, ev_g2, 0);

    // ---- final: aggregation (F=64) fused with relu + log_softmax
    k_aggregate64_softmax<<<(N * 32 + T - 1) / T, T>>>(p_h0, b2, out, N);
}

// round 13
// speedup vs baseline: 1.1374x; 1.1374x over previous
#include <cuda_runtime.h>
#include <cuda_bf16.h>
#include <cstdint>

// ---------------------------------------------------------------------------
// FCHCGNN: 3-layer GCN, CSR gather formulation (no float atomics).
// R7 structure (CSR build overlapped with layer-0 GEMM) + L2 eviction policy:
//   - agg / out stores use .cs (evict-first): single-consumer streams
//   - GEMM A-tile loads use .cs: streaming reads, keep h gather-hot in L2
// ---------------------------------------------------------------------------

#define MAXN 100000
#define MAXE 1600000

__device__ float g_h[(size_t)MAXN * 128];     // GEMM output (gather-hot in L2)
__device__ float g_agg[(size_t)MAXN * 128];   // aggregation buffer (streamed)
__device__ float g_dis[MAXN];                 // rsqrt(deg)
__device__ int   g_cnt[MAXN];
__device__ int   g_cur[MAXN];
__device__ int   g_rowptr[MAXN + 1];
__device__ int   g_esrc[MAXE];
__device__ int   g_bsum[128];
__device__ int   g_boff[130];

// ------------------------------- degree ------------------------------------
__global__ void k_deg_init(int n) {
    int i = blockIdx.x * blockDim.x + threadIdx.x;
    if (i < n) { g_cnt[i] = 0; g_cur[i] = 0; }
}

__global__ void k_deg_count(const int* __restrict__ dst, int E) {
    int e = blockIdx.x * blockDim.x + threadIdx.x;
    if (e < E) atomicAdd(&g_cnt[dst[e]], 1);
}

__global__ void k_deg_rsqrt(int n) {
    int i = blockIdx.x * blockDim.x + threadIdx.x;
    if (i < n) g_dis[i] = rsqrtf(1.0f + (float)g_cnt[i]);
}

// ----------------------- hierarchical exclusive scan ------------------------
__global__ void k_scan_local(int n) {
    const int tid = threadIdx.x, lane = tid & 31, wid = tid >> 5;
    const int i = blockIdx.x * 1024 + tid;
    int v = (i < n) ? g_cnt[i] : 0;

    int s = v;
#pragma unroll
    for (int off = 1; off < 32; off <<= 1) {
        int t = __shfl_up_sync(0xFFFFFFFFu, s, off);
        if (lane >= off) s += t;
    }
    __shared__ int wsum[32];
    if (lane == 31) wsum[wid] = s;
    __syncthreads();
    if (wid == 0) {
        int w = wsum[lane];
#pragma unroll
        for (int off = 1; off < 32; off <<= 1) {
            int t = __shfl_up_sync(0xFFFFFFFFu, w, off);
            if (lane >= off) w += t;
        }
        wsum[lane] = w;
    }
    __syncthreads();
    int base = wid ? wsum[wid - 1] : 0;
    int incl = base + s;
    if (i < n) g_rowptr[i] = incl - v;
    if (tid == 1023) g_bsum[blockIdx.x] = incl;
}

__global__ void k_scan_bsums(int nb) {
    const int tid = threadIdx.x, lane = tid & 31, wid = tid >> 5;
    int v = (tid < nb) ? g_bsum[tid] : 0;
    int s = v;
#pragma unroll
    for (int off = 1; off < 32; off <<= 1) {
        int t = __shfl_up_sync(0xFFFFFFFFu, s, off);
        if (lane >= off) s += t;
    }
    __shared__ int wsum[4];
    if (lane == 31) wsum[wid] = s;
    __syncthreads();
    int base = 0;
    for (int w = 0; w < wid; w++) base += wsum[w];
    int incl = base + s;
    if (tid < nb) g_boff[tid] = incl - v;
    if (tid == 127) g_boff[nb] = incl;
}

__global__ void k_scan_add(int n, int nb) {
    int i = blockIdx.x * 1024 + threadIdx.x;
    if (i < n) g_rowptr[i] += g_boff[blockIdx.x];
    if (i == 0) g_rowptr[n] = g_boff[nb];
}

__global__ void k_fill(const int* __restrict__ src, const int* __restrict__ dst, int E) {
    int e = blockIdx.x * blockDim.x + threadIdx.x;
    if (e < E) {
        int d = dst[e];
        int pos = g_rowptr[d] + atomicAdd(&g_cur[d], 1);
        g_esrc[pos] = src[e];
    }
}

// ------------------------------- GEMM ---------------------------------------
// H[M,BN] = relu?(X[M,128]) @ W[128,BN]. 512 thr, BM=128, BK=16, TN=4.
// A loads use .cs (streaming, single use): keep L2 for the gather-hot h.
template <int BN, int TM, bool FROM_AGG>
__global__ void __launch_bounds__(512, 2)
k_gemm(const float* __restrict__ Xin, const float* __restrict__ W, int M) {
    constexpr int BM = 128, BK = 16, TN = 4, K = 128, NTH = 512;
    __shared__ float As[2][BK * BM];
    __shared__ float Bs[2][BK * BN];

    const float* __restrict__ X = FROM_AGG ? g_agg : Xin;

    const int tid = threadIdx.x;
    const int br = blockIdx.x * BM;
    const int tCol = tid % (BN / TN);
    const int tRow = tid / (BN / TN);

    const int aRow = tid >> 2;
    const int aSeg = tid & 3;
    constexpr int B_THREADS = BK * BN / 4;
    const bool bAct = (B_THREADS == NTH) || (tid < B_THREADS);
    const int bRow = tid / (BN / 4);
    const int bCol = (tid % (BN / 4)) * 4;
    const int gr = br + aRow;

    float acc[TM][TN];
#pragma unroll
    for (int i = 0; i < TM; i++)
#pragma unroll
        for (int j = 0; j < TN; j++) acc[i][j] = 0.0f;

    float4 aP = make_float4(0.f, 0.f, 0.f, 0.f);
    float4 bP = make_float4(0.f, 0.f, 0.f, 0.f);
    if (gr < M) aP = __ldcs((const float4*)(X + (size_t)gr * K + aSeg * 4));
    if (bAct)   bP = *(const float4*)(W + (size_t)bRow * BN + bCol);
    if (FROM_AGG) {
        aP.x = fmaxf(aP.x, 0.f); aP.y = fmaxf(aP.y, 0.f);
        aP.z = fmaxf(aP.z, 0.f); aP.w = fmaxf(aP.w, 0.f);
    }
    As[0][(aSeg * 4 + 0) * BM + aRow] = aP.x;
    As[0][(aSeg * 4 + 1) * BM + aRow] = aP.y;
    As[0][(aSeg * 4 + 2) * BM + aRow] = aP.z;
    As[0][(aSeg * 4 + 3) * BM + aRow] = aP.w;
    if (bAct) *(float4*)&Bs[0][bRow * BN + bCol] = bP;
    __syncthreads();

    int buf = 0;
#pragma unroll
    for (int k0 = 0; k0 < K; k0 += BK) {
        const int nk = k0 + BK;
        if (nk < K) {
            aP = make_float4(0.f, 0.f, 0.f, 0.f);
            if (gr < M) aP = __ldcs((const float4*)(X + (size_t)gr * K + nk + aSeg * 4));
            if (bAct)   bP = *(const float4*)(W + (size_t)(nk + bRow) * BN + bCol);
            if (FROM_AGG) {
                aP.x = fmaxf(aP.x, 0.f); aP.y = fmaxf(aP.y, 0.f);
                aP.z = fmaxf(aP.z, 0.f); aP.w = fmaxf(aP.w, 0.f);
            }
        }

#pragma unroll
        for (int kk = 0; kk < BK; kk++) {
            float ra[TM], rb[TN];
#pragma unroll
            for (int i = 0; i < TM / 4; i++) {
                float4 t = *(const float4*)&As[buf][kk * BM + tRow * TM + i * 4];
                ra[i * 4 + 0] = t.x; ra[i * 4 + 1] = t.y;
                ra[i * 4 + 2] = t.z; ra[i * 4 + 3] = t.w;
            }
            {
                float4 t = *(const float4*)&Bs[buf][kk * BN + tCol * TN];
                rb[0] = t.x; rb[1] = t.y; rb[2] = t.z; rb[3] = t.w;
            }
#pragma unroll
            for (int i = 0; i < TM; i++)
#pragma unroll
                for (int j = 0; j < TN; j++) acc[i][j] += ra[i] * rb[j];
        }

        if (nk < K) {
            const int nxt = buf ^ 1;
            As[nxt][(aSeg * 4 + 0) * BM + aRow] = aP.x;
            As[nxt][(aSeg * 4 + 1) * BM + aRow] = aP.y;
            As[nxt][(aSeg * 4 + 2) * BM + aRow] = aP.z;
            As[nxt][(aSeg * 4 + 3) * BM + aRow] = aP.w;
            if (bAct) *(float4*)&Bs[nxt][bRow * BN + bCol] = bP;
            __syncthreads();
            buf = nxt;
        }
    }

    // h stores: default policy (h must stay L2-resident for the gather)
#pragma unroll
    for (int i = 0; i < TM; i++) {
        int grr = br + tRow * TM + i;
        if (grr < M) {
            float4 o = make_float4(acc[i][0], acc[i][1], acc[i][2], acc[i][3]);
            *(float4*)(g_h + (size_t)grr * BN + tCol * TN) = o;
        }
    }
}

// --------------------- gather aggregation (F=128) ---------------------------
__global__ void k_aggregate128(const float* __restrict__ bias, int n) {
    int node = (int)(((size_t)blockIdx.x * blockDim.x + threadIdx.x) >> 5);
    int lane = threadIdx.x & 31;
    if (node >= n) return;

    const float4* __restrict__ h4 = (const float4*)g_h;
    float disd = g_dis[node];

    float4 acc = ((const float4*)bias)[lane];
    {
        float nrm = disd * disd;
        float4 v = h4[(size_t)node * 32 + lane];
        acc.x += v.x * nrm; acc.y += v.y * nrm;
        acc.z += v.z * nrm; acc.w += v.w * nrm;
    }

    int e = g_rowptr[node];
    int end = g_rowptr[node + 1];
    for (; e + 3 < end; e += 4) {
        int s0 = g_esrc[e],     s1 = g_esrc[e + 1];
        int s2 = g_esrc[e + 2], s3 = g_esrc[e + 3];
        float n0 = g_dis[s0] * disd, n1 = g_dis[s1] * disd;
        float n2 = g_dis[s2] * disd, n3 = g_dis[s3] * disd;
        float4 v0 = h4[(size_t)s0 * 32 + lane];
        float4 v1 = h4[(size_t)s1 * 32 + lane];
        float4 v2 = h4[(size_t)s2 * 32 + lane];
        float4 v3 = h4[(size_t)s3 * 32 + lane];
        acc.x += v0.x * n0 + v1.x * n1 + v2.x * n2 + v3.x * n3;
        acc.y += v0.y * n0 + v1.y * n1 + v2.y * n2 + v3.y * n3;
        acc.z += v0.z * n0 + v1.z * n1 + v2.z * n2 + v3.z * n3;
        acc.w += v0.w * n0 + v1.w * n1 + v2.w * n2 + v3.w * n3;
    }
    for (; e < end; e++) {
        int s0 = g_esrc[e];
        float n0 = g_dis[s0] * disd;
        float4 v0 = h4[(size_t)s0 * 32 + lane];
        acc.x += v0.x * n0; acc.y += v0.y * n0;
        acc.z += v0.z * n0; acc.w += v0.w * n0;
    }

    // evict-first store: agg is read exactly once (by the next GEMM)
    __stcs(((float4*)g_agg) + (size_t)node * 32 + lane, acc);
}

// ------- gather aggregation (F=64) fused with relu + log_softmax ------------
__global__ void k_aggregate64_softmax(const float* __restrict__ bias,
                                      float* __restrict__ out, int n) {
    int node = (int)(((size_t)blockIdx.x * blockDim.x + threadIdx.x) >> 5);
    int lane = threadIdx.x & 31;
    if (node >= n) return;

    const float2* __restrict__ h2 = (const float2*)g_h;
    float disd = g_dis[node];

    float2 acc = ((const float2*)bias)[lane];
    {
        float nrm = disd * disd;
        float2 v = h2[(size_t)node * 32 + lane];
        acc.x += v.x * nrm; acc.y += v.y * nrm;
    }

    int e = g_rowptr[node];
    int end = g_rowptr[node + 1];
    for (; e + 3 < end; e += 4) {
        int s0 = g_esrc[e],     s1 = g_esrc[e + 1];
        int s2 = g_esrc[e + 2], s3 = g_esrc[e + 3];
        float n0 = g_dis[s0] * disd, n1 = g_dis[s1] * disd;
        float n2 = g_dis[s2] * disd, n3 = g_dis[s3] * disd;
        float2 v0 = h2[(size_t)s0 * 32 + lane];
        float2 v1 = h2[(size_t)s1 * 32 + lane];
        float2 v2 = h2[(size_t)s2 * 32 + lane];
        float2 v3 = h2[(size_t)s3 * 32 + lane];
        acc.x += v0.x * n0 + v1.x * n1 + v2.x * n2 + v3.x * n3;
        acc.y += v0.y * n0 + v1.y * n1 + v2.y * n2 + v3.y * n3;
    }
    for (; e < end; e++) {
        int s0 = g_esrc[e];
        float n0 = g_dis[s0] * disd;
        float2 v0 = h2[(size_t)s0 * 32 + lane];
        acc.x += v0.x * n0; acc.y += v0.y * n0;
    }

    acc.x = fmaxf(acc.x, 0.f);
    acc.y = fmaxf(acc.y, 0.f);

    float m = fmaxf(acc.x, acc.y);
#pragma unroll
    for (int off = 16; off; off >>= 1) m = fmaxf(m, __shfl_xor_sync(0xFFFFFFFFu, m, off));

    float ssum = expf(acc.x - m) + expf(acc.y - m);
#pragma unroll
    for (int off = 16; off; off >>= 1) ssum += __shfl_xor_sync(0xFFFFFFFFu, ssum, off);

    float l = logf(ssum);
    float2 o;
    o.x = acc.x - m - l;
    o.y = acc.y - m - l;
    __stcs(((float2*)out) + (size_t)node * 32 + lane, o);
}

// ----------------------------------------------------------------------------
extern "C" void kernel_launch(void* const* d_in, const int* in_sizes, int n_in,
                              void* d_out, int out_size) {
    const float* x  = (const float*)d_in[0];
    const int* ei   = (const int*)d_in[1];
    const float* W0 = (const float*)d_in[2];
    const float* b0 = (const float*)d_in[3];
    const float* W1 = (const float*)d_in[4];
    const float* b1 = (const float*)d_in[5];
    const float* W2 = (const float*)d_in[6];
    const float* b2 = (const float*)d_in[7];
    float* out = (float*)d_out;

    const int N = in_sizes[0] / 128;
    const int E = in_sizes[1] / 2;
    const int* src = ei;
    const int* dst = ei + E;

    const int T = 256;
    const int nb = (N + 1023) / 1024;

    // one-time side stream + events (created on the uncaptured correctness call)
    static cudaStream_t s_side = nullptr;
    static cudaEvent_t ev_fork = nullptr, ev_csr = nullptr;
    if (s_side == nullptr) {
        cudaStreamCreateWithFlags(&s_side, cudaStreamNonBlocking);
        cudaEventCreateWithFlags(&ev_fork, cudaEventDisableTiming);
        cudaEventCreateWithFlags(&ev_csr, cudaEventDisableTiming);
    }

    // ---- fork: CSR build on side stream, GEMM-0 on main stream
    cudaEventRecord(ev_fork, 0);
    cudaStreamWaitEvent(s_side, ev_fork, 0);

    k_deg_init<<<(N + T - 1) / T, T, 0, s_side>>>(N);
    k_deg_count<<<(E + T - 1) / T, T, 0, s_side>>>(dst, E);
    k_deg_rsqrt<<<(N + T - 1) / T, T, 0, s_side>>>(N);
    k_scan_local<<<nb, 1024, 0, s_side>>>(N);
    k_scan_bsums<<<1, 128, 0, s_side>>>(nb);
    k_scan_add<<<nb, 1024, 0, s_side>>>(N, nb);
    k_fill<<<(E + T - 1) / T, T, 0, s_side>>>(src, dst, E);
    cudaEventRecord(ev_csr, s_side);

    const int gemmBlocks = (N + 127) / 128;
    const int aggBlocks = (N * 32 + T - 1) / T;

    // ---- layer 0: 128 -> 128 (GEMM concurrent with CSR build)
    k_gemm<128, 8, false><<<gemmBlocks, 512>>>(x, W0, N);

    cudaStreamWaitEvent(0, ev_csr, 0);   // join: aggregation needs CSR + dis

    k_aggregate128<<<aggBlocks, T>>>(b0, N);

    // ---- layer 1: 128 -> 128 (relu fused into GEMM A load)
    k_gemm<128, 8, true><<<gemmBlocks, 512>>>(nullptr, W1, N);
    k_aggregate128<<<aggBlocks, T>>>(b1, N);

    // ---- layer 2: 128 -> 64, aggregation fused with relu + log_softmax
    k_gemm<64, 4, true><<<gemmBlocks, 512>>>(nullptr, W2, N);
    k_aggregate64_softmax<<<aggBlocks, T>>>(b2, out, N);
}

// round 15
// speedup vs baseline: 1.1784x; 1.0361x over previous
#include <cuda_runtime.h>
#include <cuda_bf16.h>
#include <cstdint>

// ---------------------------------------------------------------------------
// FCHCGNN: 3-layer GCN, CSR gather formulation (no float atomics).
// R13 structure + packed fp32x2 FMA (Blackwell FFMA2) in the GEMM inner loop.
// ---------------------------------------------------------------------------

#define MAXN 100000
#define MAXE 1600000

__device__ float g_h[(size_t)MAXN * 128];     // GEMM output (gather-hot in L2)
__device__ float g_agg[(size_t)MAXN * 128];   // aggregation buffer (streamed)
__device__ float g_dis[MAXN];                 // rsqrt(deg)
__device__ int   g_cnt[MAXN];
__device__ int   g_cur[MAXN];
__device__ int   g_rowptr[MAXN + 1];
__device__ int   g_esrc[MAXE];
__device__ int   g_bsum[128];
__device__ int   g_boff[130];

// ---- packed f32x2 helpers (sm_100+) ----------------------------------------
__device__ __forceinline__ unsigned long long pack_f32x2(float lo, float hi) {
    unsigned long long r;
    asm("mov.b64 %0, {%1, %2};" : "=l"(r) : "f"(lo), "f"(hi));
    return r;
}
__device__ __forceinline__ unsigned long long fma_f32x2(
    unsigned long long a, unsigned long long b, unsigned long long c) {
    unsigned long long d;
    asm("fma.rn.f32x2 %0, %1, %2, %3;" : "=l"(d) : "l"(a), "l"(b), "l"(c));
    return d;
}
__device__ __forceinline__ void unpack_f32x2(unsigned long long v, float& lo, float& hi) {
    asm("mov.b64 {%0, %1}, %2;" : "=f"(lo), "=f"(hi) : "l"(v));
}

// ------------------------------- degree ------------------------------------
__global__ void k_deg_init(int n) {
    int i = blockIdx.x * blockDim.x + threadIdx.x;
    if (i < n) { g_cnt[i] = 0; g_cur[i] = 0; }
}

__global__ void k_deg_count(const int* __restrict__ dst, int E) {
    int e = blockIdx.x * blockDim.x + threadIdx.x;
    if (e < E) atomicAdd(&g_cnt[dst[e]], 1);
}

__global__ void k_deg_rsqrt(int n) {
    int i = blockIdx.x * blockDim.x + threadIdx.x;
    if (i < n) g_dis[i] = rsqrtf(1.0f + (float)g_cnt[i]);
}

// ----------------------- hierarchical exclusive scan ------------------------
__global__ void k_scan_local(int n) {
    const int tid = threadIdx.x, lane = tid & 31, wid = tid >> 5;
    const int i = blockIdx.x * 1024 + tid;
    int v = (i < n) ? g_cnt[i] : 0;

    int s = v;
#pragma unroll
    for (int off = 1; off < 32; off <<= 1) {
        int t = __shfl_up_sync(0xFFFFFFFFu, s, off);
        if (lane >= off) s += t;
    }
    __shared__ int wsum[32];
    if (lane == 31) wsum[wid] = s;
    __syncthreads();
    if (wid == 0) {
        int w = wsum[lane];
#pragma unroll
        for (int off = 1; off < 32; off <<= 1) {
            int t = __shfl_up_sync(0xFFFFFFFFu, w, off);
            if (lane >= off) w += t;
        }
        wsum[lane] = w;
    }
    __syncthreads();
    int base = wid ? wsum[wid - 1] : 0;
    int incl = base + s;
    if (i < n) g_rowptr[i] = incl - v;
    if (tid == 1023) g_bsum[blockIdx.x] = incl;
}

__global__ void k_scan_bsums(int nb) {
    const int tid = threadIdx.x, lane = tid & 31, wid = tid >> 5;
    int v = (tid < nb) ? g_bsum[tid] : 0;
    int s = v;
#pragma unroll
    for (int off = 1; off < 32; off <<= 1) {
        int t = __shfl_up_sync(0xFFFFFFFFu, s, off);
        if (lane >= off) s += t;
    }
    __shared__ int wsum[4];
    if (lane == 31) wsum[wid] = s;
    __syncthreads();
    int base = 0;
    for (int w = 0; w < wid; w++) base += wsum[w];
    int incl = base + s;
    if (tid < nb) g_boff[tid] = incl - v;
    if (tid == 127) g_boff[nb] = incl;
}

__global__ void k_scan_add(int n, int nb) {
    int i = blockIdx.x * 1024 + threadIdx.x;
    if (i < n) g_rowptr[i] += g_boff[blockIdx.x];
    if (i == 0) g_rowptr[n] = g_boff[nb];
}

__global__ void k_fill(const int* __restrict__ src, const int* __restrict__ dst, int E) {
    int e = blockIdx.x * blockDim.x + threadIdx.x;
    if (e < E) {
        int d = dst[e];
        int pos = g_rowptr[d] + atomicAdd(&g_cur[d], 1);
        g_esrc[pos] = src[e];
    }
}

// ------------------------------- GEMM ---------------------------------------
// H[M,BN] = relu?(X[M,128]) @ W[128,BN]. 512 thr, BM=128, BK=16, TN=4.
// Inner loop uses packed fp32x2 FMA (FFMA2): A pairs come packed from LDS.128
// (rows contiguous in As), B components are dup-packed. Bit-identical fp32.
template <int BN, int TM, bool FROM_AGG>
__global__ void __launch_bounds__(512, 2)
k_gemm(const float* __restrict__ Xin, const float* __restrict__ W, int M) {
    constexpr int BM = 128, BK = 16, TN = 4, K = 128, NTH = 512;
    __shared__ float As[2][BK * BM];
    __shared__ float Bs[2][BK * BN];

    const float* __restrict__ X = FROM_AGG ? g_agg : Xin;

    const int tid = threadIdx.x;
    const int br = blockIdx.x * BM;
    const int tCol = tid % (BN / TN);
    const int tRow = tid / (BN / TN);

    const int aRow = tid >> 2;
    const int aSeg = tid & 3;
    constexpr int B_THREADS = BK * BN / 4;
    const bool bAct = (B_THREADS == NTH) || (tid < B_THREADS);
    const int bRow = tid / (BN / 4);
    const int bCol = (tid % (BN / 4)) * 4;
    const int gr = br + aRow;

    constexpr int TP = TM / 2;                 // packed row pairs
    unsigned long long acc2[TP][TN];
#pragma unroll
    for (int p = 0; p < TP; p++)
#pragma unroll
        for (int j = 0; j < TN; j++) acc2[p][j] = 0ull;

    float4 aP = make_float4(0.f, 0.f, 0.f, 0.f);
    float4 bP = make_float4(0.f, 0.f, 0.f, 0.f);
    if (gr < M) aP = __ldcs((const float4*)(X + (size_t)gr * K + aSeg * 4));
    if (bAct)   bP = *(const float4*)(W + (size_t)bRow * BN + bCol);
    if (FROM_AGG) {
        aP.x = fmaxf(aP.x, 0.f); aP.y = fmaxf(aP.y, 0.f);
        aP.z = fmaxf(aP.z, 0.f); aP.w = fmaxf(aP.w, 0.f);
    }
    As[0][(aSeg * 4 + 0) * BM + aRow] = aP.x;
    As[0][(aSeg * 4 + 1) * BM + aRow] = aP.y;
    As[0][(aSeg * 4 + 2) * BM + aRow] = aP.z;
    As[0][(aSeg * 4 + 3) * BM + aRow] = aP.w;
    if (bAct) *(float4*)&Bs[0][bRow * BN + bCol] = bP;
    __syncthreads();

    int buf = 0;
#pragma unroll
    for (int k0 = 0; k0 < K; k0 += BK) {
        const int nk = k0 + BK;
        if (nk < K) {
            aP = make_float4(0.f, 0.f, 0.f, 0.f);
            if (gr < M) aP = __ldcs((const float4*)(X + (size_t)gr * K + nk + aSeg * 4));
            if (bAct)   bP = *(const float4*)(W + (size_t)(nk + bRow) * BN + bCol);
            if (FROM_AGG) {
                aP.x = fmaxf(aP.x, 0.f); aP.y = fmaxf(aP.y, 0.f);
                aP.z = fmaxf(aP.z, 0.f); aP.w = fmaxf(aP.w, 0.f);
            }
        }

#pragma unroll
        for (int kk = 0; kk < BK; kk++) {
            // A fragment: TM contiguous floats -> TP packed f32x2 pairs
            unsigned long long a2[TP];
#pragma unroll
            for (int q = 0; q < TM / 4; q++) {
                ulonglong2 t = *(const ulonglong2*)&As[buf][kk * BM + tRow * TM + q * 4];
                a2[q * 2 + 0] = t.x;
                a2[q * 2 + 1] = t.y;
            }
            // B fragment: 4 floats, dup-packed
            unsigned long long bb[TN];
            {
                float4 t = *(const float4*)&Bs[buf][kk * BN + tCol * TN];
                bb[0] = pack_f32x2(t.x, t.x);
                bb[1] = pack_f32x2(t.y, t.y);
                bb[2] = pack_f32x2(t.z, t.z);
                bb[3] = pack_f32x2(t.w, t.w);
            }
#pragma unroll
            for (int p = 0; p < TP; p++)
#pragma unroll
                for (int j = 0; j < TN; j++)
                    acc2[p][j] = fma_f32x2(a2[p], bb[j], acc2[p][j]);
        }

        if (nk < K) {
            const int nxt = buf ^ 1;
            As[nxt][(aSeg * 4 + 0) * BM + aRow] = aP.x;
            As[nxt][(aSeg * 4 + 1) * BM + aRow] = aP.y;
            As[nxt][(aSeg * 4 + 2) * BM + aRow] = aP.z;
            As[nxt][(aSeg * 4 + 3) * BM + aRow] = aP.w;
            if (bAct) *(float4*)&Bs[nxt][bRow * BN + bCol] = bP;
            __syncthreads();
            buf = nxt;
        }
    }

    // epilogue: unpack pairs; lo -> row 2p, hi -> row 2p+1
#pragma unroll
    for (int p = 0; p < TP; p++) {
        float lo0, hi0, lo1, hi1, lo2, hi2, lo3, hi3;
        unpack_f32x2(acc2[p][0], lo0, hi0);
        unpack_f32x2(acc2[p][1], lo1, hi1);
        unpack_f32x2(acc2[p][2], lo2, hi2);
        unpack_f32x2(acc2[p][3], lo3, hi3);
        int r0 = br + tRow * TM + 2 * p;
        if (r0 < M)
            *(float4*)(g_h + (size_t)r0 * BN + tCol * TN) =
                make_float4(lo0, lo1, lo2, lo3);
        if (r0 + 1 < M)
            *(float4*)(g_h + (size_t)(r0 + 1) * BN + tCol * TN) =
                make_float4(hi0, hi1, hi2, hi3);
    }
}

// --------------------- gather aggregation (F=128) ---------------------------
__global__ void k_aggregate128(const float* __restrict__ bias, int n) {
    int node = (int)(((size_t)blockIdx.x * blockDim.x + threadIdx.x) >> 5);
    int lane = threadIdx.x & 31;
    if (node >= n) return;

    const float4* __restrict__ h4 = (const float4*)g_h;
    float disd = g_dis[node];

    float4 acc = ((const float4*)bias)[lane];
    {
        float nrm = disd * disd;
        float4 v = h4[(size_t)node * 32 + lane];
        acc.x += v.x * nrm; acc.y += v.y * nrm;
        acc.z += v.z * nrm; acc.w += v.w * nrm;
    }

    int e = g_rowptr[node];
    int end = g_rowptr[node + 1];
    for (; e + 3 < end; e += 4) {
        int s0 = g_esrc[e],     s1 = g_esrc[e + 1];
        int s2 = g_esrc[e + 2], s3 = g_esrc[e + 3];
        float n0 = g_dis[s0] * disd, n1 = g_dis[s1] * disd;
        float n2 = g_dis[s2] * disd, n3 = g_dis[s3] * disd;
        float4 v0 = h4[(size_t)s0 * 32 + lane];
        float4 v1 = h4[(size_t)s1 * 32 + lane];
        float4 v2 = h4[(size_t)s2 * 32 + lane];
        float4 v3 = h4[(size_t)s3 * 32 + lane];
        acc.x += v0.x * n0 + v1.x * n1 + v2.x * n2 + v3.x * n3;
        acc.y += v0.y * n0 + v1.y * n1 + v2.y * n2 + v3.y * n3;
        acc.z += v0.z * n0 + v1.z * n1 + v2.z * n2 + v3.z * n3;
        acc.w += v0.w * n0 + v1.w * n1 + v2.w * n2 + v3.w * n3;
    }
    for (; e < end; e++) {
        int s0 = g_esrc[e];
        float n0 = g_dis[s0] * disd;
        float4 v0 = h4[(size_t)s0 * 32 + lane];
        acc.x += v0.x * n0; acc.y += v0.y * n0;
        acc.z += v0.z * n0; acc.w += v0.w * n0;
    }

    // evict-first store: agg is read exactly once (by the next GEMM)
    __stcs(((float4*)g_agg) + (size_t)node * 32 + lane, acc);
}

// ------- gather aggregation (F=64) fused with relu + log_softmax ------------
__global__ void k_aggregate64_softmax(const float* __restrict__ bias,
                                      float* __restrict__ out, int n) {
    int node = (int)(((size_t)blockIdx.x * blockDim.x + threadIdx.x) >> 5);
    int lane = threadIdx.x & 31;
    if (node >= n) return;

    const float2* __restrict__ h2 = (const float2*)g_h;
    float disd = g_dis[node];

    float2 acc = ((const float2*)bias)[lane];
    {
        float nrm = disd * disd;
        float2 v = h2[(size_t)node * 32 + lane];
        acc.x += v.x * nrm; acc.y += v.y * nrm;
    }

    int e = g_rowptr[node];
    int end = g_rowptr[node + 1];
    for (; e + 3 < end; e += 4) {
        int s0 = g_esrc[e],     s1 = g_esrc[e + 1];
        int s2 = g_esrc[e + 2], s3 = g_esrc[e + 3];
        float n0 = g_dis[s0] * disd, n1 = g_dis[s1] * disd;
        float n2 = g_dis[s2] * disd, n3 = g_dis[s3] * disd;
        float2 v0 = h2[(size_t)s0 * 32 + lane];
        float2 v1 = h2[(size_t)s1 * 32 + lane];
        float2 v2 = h2[(size_t)s2 * 32 + lane];
        float2 v3 = h2[(size_t)s3 * 32 + lane];
        acc.x += v0.x * n0 + v1.x * n1 + v2.x * n2 + v3.x * n3;
        acc.y += v0.y * n0 + v1.y * n1 + v2.y * n2 + v3.y * n3;
    }
    for (; e < end; e++) {
        int s0 = g_esrc[e];
        float n0 = g_dis[s0] * disd;
        float2 v0 = h2[(size_t)s0 * 32 + lane];
        acc.x += v0.x * n0; acc.y += v0.y * n0;
    }

    acc.x = fmaxf(acc.x, 0.f);
    acc.y = fmaxf(acc.y, 0.f);

    float m = fmaxf(acc.x, acc.y);
#pragma unroll
    for (int off = 16; off; off >>= 1) m = fmaxf(m, __shfl_xor_sync(0xFFFFFFFFu, m, off));

    float ssum = expf(acc.x - m) + expf(acc.y - m);
#pragma unroll
    for (int off = 16; off; off >>= 1) ssum += __shfl_xor_sync(0xFFFFFFFFu, ssum, off);

    float l = logf(ssum);
    float2 o;
    o.x = acc.x - m - l;
    o.y = acc.y - m - l;
    __stcs(((float2*)out) + (size_t)node * 32 + lane, o);
}

// ----------------------------------------------------------------------------
extern "C" void kernel_launch(void* const* d_in, const int* in_sizes, int n_in,
                              void* d_out, int out_size) {
    const float* x  = (const float*)d_in[0];
    const int* ei   = (const int*)d_in[1];
    const float* W0 = (const float*)d_in[2];
    const float* b0 = (const float*)d_in[3];
    const float* W1 = (const float*)d_in[4];
    const float* b1 = (const float*)d_in[5];
    const float* W2 = (const float*)d_in[6];
    const float* b2 = (const float*)d_in[7];
    float* out = (float*)d_out;

    const int N = in_sizes[0] / 128;
    const int E = in_sizes[1] / 2;
    const int* src = ei;
    const int* dst = ei + E;

    const int T = 256;
    const int nb = (N + 1023) / 1024;

    // one-time side stream + events (created on the uncaptured correctness call)
    static cudaStream_t s_side = nullptr;
    static cudaEvent_t ev_fork = nullptr, ev_csr = nullptr;
    if (s_side == nullptr) {
        cudaStreamCreateWithFlags(&s_side, cudaStreamNonBlocking);
        cudaEventCreateWithFlags(&ev_fork, cudaEventDisableTiming);
        cudaEventCreateWithFlags(&ev_csr, cudaEventDisableTiming);
    }

    // ---- fork: CSR build on side stream, GEMM-0 on main stream
    cudaEventRecord(ev_fork, 0);
    cudaStreamWaitEvent(s_side, ev_fork, 0);

    k_deg_init<<<(N + T - 1) / T, T, 0, s_side>>>(N);
    k_deg_count<<<(E + T - 1) / T, T, 0, s_side>>>(dst, E);
    k_deg_rsqrt<<<(N + T - 1) / T, T, 0, s_side>>>(N);
    k_scan_local<<<nb, 1024, 0, s_side>>>(N);
    k_scan_bsums<<<1, 128, 0, s_side>>>(nb);
    k_scan_add<<<nb, 1024, 0, s_side>>>(N, nb);
    k_fill<<<(E + T - 1) / T, T, 0, s_side>>>(src, dst, E);
    cudaEventRecord(ev_csr, s_side);

    const int gemmBlocks = (N + 127) / 128;
    const int aggBlocks = (N * 32 + T - 1) / T;

    // ---- layer 0: 128 -> 128 (GEMM concurrent with CSR build)
    k_gemm<128, 8, false><<<gemmBlocks, 512>>>(x, W0, N);

    cudaStreamWaitEvent(0, ev_csr, 0);   // join: aggregation needs CSR + dis

    k_aggregate128<<<aggBlocks, T>>>(b0, N);

    // ---- layer 1: 128 -> 128 (relu fused into GEMM A load)
    k_gemm<128, 8, true><<<gemmBlocks, 512>>>(nullptr, W1, N);
    k_aggregate128<<<aggBlocks, T>>>(b1, N);

    // ---- layer 2: 128 -> 64, aggregation fused with relu + log_softmax
    k_gemm<64, 4, true><<<gemmBlocks, 512>>>(nullptr, W2, N);
    k_aggregate64_softmax<<<aggBlocks, T>>>(b2, out, N);
}

// round 17
// speedup vs baseline: 1.3212x; 1.1212x over previous
#include <cuda_runtime.h>
#include <cuda_fp16.h>
#include <cuda_bf16.h>
#include <cstdint>

// ---------------------------------------------------------------------------
// FCHCGNN: 3-layer GCN, CSR gather formulation (no float atomics).
// R15 structure + fp16 h buffer: gather payload halved (accumulate in fp32).
// ---------------------------------------------------------------------------

#define MAXN 100000
#define MAXE 1600000

__device__ __half g_h[(size_t)MAXN * 128];    // GEMM output, fp16 (gather-hot)
__device__ float  g_agg[(size_t)MAXN * 128];  // aggregation buffer (fp32, streamed)
__device__ float  g_dis[MAXN];                // rsqrt(deg)
__device__ int    g_cnt[MAXN];
__device__ int    g_cur[MAXN];
__device__ int    g_rowptr[MAXN + 1];
__device__ int    g_esrc[MAXE];
__device__ int    g_bsum[128];
__device__ int    g_boff[130];

// ---- packed f32x2 helpers (sm_100+) ----------------------------------------
__device__ __forceinline__ unsigned long long pack_f32x2(float lo, float hi) {
    unsigned long long r;
    asm("mov.b64 %0, {%1, %2};" : "=l"(r) : "f"(lo), "f"(hi));
    return r;
}
__device__ __forceinline__ unsigned long long fma_f32x2(
    unsigned long long a, unsigned long long b, unsigned long long c) {
    unsigned long long d;
    asm("fma.rn.f32x2 %0, %1, %2, %3;" : "=l"(d) : "l"(a), "l"(b), "l"(c));
    return d;
}
__device__ __forceinline__ void unpack_f32x2(unsigned long long v, float& lo, float& hi) {
    asm("mov.b64 {%0, %1}, %2;" : "=f"(lo), "=f"(hi) : "l"(v));
}

// store 4 floats as 4 contiguous halves (8B)
__device__ __forceinline__ void st_h4(__half* p, float a, float b, float c, float d) {
    __half2 lo = __floats2half2_rn(a, b);
    __half2 hi = __floats2half2_rn(c, d);
    uint2 v;
    v.x = *reinterpret_cast<unsigned*>(&lo);
    v.y = *reinterpret_cast<unsigned*>(&hi);
    *reinterpret_cast<uint2*>(p) = v;
}

// ------------------------------- degree ------------------------------------
__global__ void k_deg_init(int n) {
    int i = blockIdx.x * blockDim.x + threadIdx.x;
    if (i < n) { g_cnt[i] = 0; g_cur[i] = 0; }
}

__global__ void k_deg_count(const int* __restrict__ dst, int E) {
    int e = blockIdx.x * blockDim.x + threadIdx.x;
    if (e < E) atomicAdd(&g_cnt[dst[e]], 1);
}

__global__ void k_deg_rsqrt(int n) {
    int i = blockIdx.x * blockDim.x + threadIdx.x;
    if (i < n) g_dis[i] = rsqrtf(1.0f + (float)g_cnt[i]);
}

// ----------------------- hierarchical exclusive scan ------------------------
__global__ void k_scan_local(int n) {
    const int tid = threadIdx.x, lane = tid & 31, wid = tid >> 5;
    const int i = blockIdx.x * 1024 + tid;
    int v = (i < n) ? g_cnt[i] : 0;

    int s = v;
#pragma unroll
    for (int off = 1; off < 32; off <<= 1) {
        int t = __shfl_up_sync(0xFFFFFFFFu, s, off);
        if (lane >= off) s += t;
    }
    __shared__ int wsum[32];
    if (lane == 31) wsum[wid] = s;
    __syncthreads();
    if (wid == 0) {
        int w = wsum[lane];
#pragma unroll
        for (int off = 1; off < 32; off <<= 1) {
            int t = __shfl_up_sync(0xFFFFFFFFu, w, off);
            if (lane >= off) w += t;
        }
        wsum[lane] = w;
    }
    __syncthreads();
    int base = wid ? wsum[wid - 1] : 0;
    int incl = base + s;
    if (i < n) g_rowptr[i] = incl - v;
    if (tid == 1023) g_bsum[blockIdx.x] = incl;
}

__global__ void k_scan_bsums(int nb) {
    const int tid = threadIdx.x, lane = tid & 31, wid = tid >> 5;
    int v = (tid < nb) ? g_bsum[tid] : 0;
    int s = v;
#pragma unroll
    for (int off = 1; off < 32; off <<= 1) {
        int t = __shfl_up_sync(0xFFFFFFFFu, s, off);
        if (lane >= off) s += t;
    }
    __shared__ int wsum[4];
    if (lane == 31) wsum[wid] = s;
    __syncthreads();
    int base = 0;
    for (int w = 0; w < wid; w++) base += wsum[w];
    int incl = base + s;
    if (tid < nb) g_boff[tid] = incl - v;
    if (tid == 127) g_boff[nb] = incl;
}

__global__ void k_scan_add(int n, int nb) {
    int i = blockIdx.x * 1024 + threadIdx.x;
    if (i < n) g_rowptr[i] += g_boff[blockIdx.x];
    if (i == 0) g_rowptr[n] = g_boff[nb];
}

__global__ void k_fill(const int* __restrict__ src, const int* __restrict__ dst, int E) {
    int e = blockIdx.x * blockDim.x + threadIdx.x;
    if (e < E) {
        int d = dst[e];
        int pos = g_rowptr[d] + atomicAdd(&g_cur[d], 1);
        g_esrc[pos] = src[e];
    }
}

// ------------------------------- GEMM ---------------------------------------
// H[M,BN] = relu?(X[M,128]) @ W[128,BN]. 512 thr, BM=128, BK=16, TN=4.
// FFMA2 inner loop; epilogue converts to fp16 (h is gather-only).
template <int BN, int TM, bool FROM_AGG>
__global__ void __launch_bounds__(512, 2)
k_gemm(const float* __restrict__ Xin, const float* __restrict__ W, int M) {
    constexpr int BM = 128, BK = 16, TN = 4, K = 128, NTH = 512;
    __shared__ float As[2][BK * BM];
    __shared__ float Bs[2][BK * BN];

    const float* __restrict__ X = FROM_AGG ? g_agg : Xin;

    const int tid = threadIdx.x;
    const int br = blockIdx.x * BM;
    const int tCol = tid % (BN / TN);
    const int tRow = tid / (BN / TN);

    const int aRow = tid >> 2;
    const int aSeg = tid & 3;
    constexpr int B_THREADS = BK * BN / 4;
    const bool bAct = (B_THREADS == NTH) || (tid < B_THREADS);
    const int bRow = tid / (BN / 4);
    const int bCol = (tid % (BN / 4)) * 4;
    const int gr = br + aRow;

    constexpr int TP = TM / 2;
    unsigned long long acc2[TP][TN];
#pragma unroll
    for (int p = 0; p < TP; p++)
#pragma unroll
        for (int j = 0; j < TN; j++) acc2[p][j] = 0ull;

    float4 aP = make_float4(0.f, 0.f, 0.f, 0.f);
    float4 bP = make_float4(0.f, 0.f, 0.f, 0.f);
    if (gr < M) aP = __ldcs((const float4*)(X + (size_t)gr * K + aSeg * 4));
    if (bAct)   bP = *(const float4*)(W + (size_t)bRow * BN + bCol);
    if (FROM_AGG) {
        aP.x = fmaxf(aP.x, 0.f); aP.y = fmaxf(aP.y, 0.f);
        aP.z = fmaxf(aP.z, 0.f); aP.w = fmaxf(aP.w, 0.f);
    }
    As[0][(aSeg * 4 + 0) * BM + aRow] = aP.x;
    As[0][(aSeg * 4 + 1) * BM + aRow] = aP.y;
    As[0][(aSeg * 4 + 2) * BM + aRow] = aP.z;
    As[0][(aSeg * 4 + 3) * BM + aRow] = aP.w;
    if (bAct) *(float4*)&Bs[0][bRow * BN + bCol] = bP;
    __syncthreads();

    int buf = 0;
#pragma unroll
    for (int k0 = 0; k0 < K; k0 += BK) {
        const int nk = k0 + BK;
        if (nk < K) {
            aP = make_float4(0.f, 0.f, 0.f, 0.f);
            if (gr < M) aP = __ldcs((const float4*)(X + (size_t)gr * K + nk + aSeg * 4));
            if (bAct)   bP = *(const float4*)(W + (size_t)(nk + bRow) * BN + bCol);
            if (FROM_AGG) {
                aP.x = fmaxf(aP.x, 0.f); aP.y = fmaxf(aP.y, 0.f);
                aP.z = fmaxf(aP.z, 0.f); aP.w = fmaxf(aP.w, 0.f);
            }
        }

#pragma unroll
        for (int kk = 0; kk < BK; kk++) {
            unsigned long long a2[TP];
#pragma unroll
            for (int q = 0; q < TM / 4; q++) {
                ulonglong2 t = *(const ulonglong2*)&As[buf][kk * BM + tRow * TM + q * 4];
                a2[q * 2 + 0] = t.x;
                a2[q * 2 + 1] = t.y;
            }
            unsigned long long bb[TN];
            {
                float4 t = *(const float4*)&Bs[buf][kk * BN + tCol * TN];
                bb[0] = pack_f32x2(t.x, t.x);
                bb[1] = pack_f32x2(t.y, t.y);
                bb[2] = pack_f32x2(t.z, t.z);
                bb[3] = pack_f32x2(t.w, t.w);
            }
#pragma unroll
            for (int p = 0; p < TP; p++)
#pragma unroll
                for (int j = 0; j < TN; j++)
                    acc2[p][j] = fma_f32x2(a2[p], bb[j], acc2[p][j]);
        }

        if (nk < K) {
            const int nxt = buf ^ 1;
            As[nxt][(aSeg * 4 + 0) * BM + aRow] = aP.x;
            As[nxt][(aSeg * 4 + 1) * BM + aRow] = aP.y;
            As[nxt][(aSeg * 4 + 2) * BM + aRow] = aP.z;
            As[nxt][(aSeg * 4 + 3) * BM + aRow] = aP.w;
            if (bAct) *(float4*)&Bs[nxt][bRow * BN + bCol] = bP;
            __syncthreads();
            buf = nxt;
        }
    }

    // epilogue: unpack pairs, convert to fp16; lo -> row 2p, hi -> row 2p+1
#pragma unroll
    for (int p = 0; p < TP; p++) {
        float lo0, hi0, lo1, hi1, lo2, hi2, lo3, hi3;
        unpack_f32x2(acc2[p][0], lo0, hi0);
        unpack_f32x2(acc2[p][1], lo1, hi1);
        unpack_f32x2(acc2[p][2], lo2, hi2);
        unpack_f32x2(acc2[p][3], lo3, hi3);
        int r0 = br + tRow * TM + 2 * p;
        if (r0 < M)
            st_h4(g_h + (size_t)r0 * BN + tCol * TN, lo0, lo1, lo2, lo3);
        if (r0 + 1 < M)
            st_h4(g_h + (size_t)(r0 + 1) * BN + tCol * TN, hi0, hi1, hi2, hi3);
    }
}

// --------------------- gather aggregation (F=128, fp16 h) -------------------
// one warp per node; lane owns 4 features (8B = 4 halves per row)
__device__ __forceinline__ void acc_h4(float4& acc, uint2 r, float nrm) {
    __half2 a = *reinterpret_cast<__half2*>(&r.x);
    __half2 b = *reinterpret_cast<__half2*>(&r.y);
    float2 f0 = __half22float2(a);
    float2 f1 = __half22float2(b);
    acc.x += f0.x * nrm; acc.y += f0.y * nrm;
    acc.z += f1.x * nrm; acc.w += f1.y * nrm;
}

__global__ void k_aggregate128(const float* __restrict__ bias, int n) {
    int node = (int)(((size_t)blockIdx.x * blockDim.x + threadIdx.x) >> 5);
    int lane = threadIdx.x & 31;
    if (node >= n) return;

    const uint2* __restrict__ hv = (const uint2*)g_h;  // 32 uint2 per row
    float disd = g_dis[node];

    float4 acc = ((const float4*)bias)[lane];
    acc_h4(acc, hv[(size_t)node * 32 + lane], disd * disd);  // self loop

    int e = g_rowptr[node];
    int end = g_rowptr[node + 1];
    for (; e + 3 < end; e += 4) {
        int s0 = g_esrc[e],     s1 = g_esrc[e + 1];
        int s2 = g_esrc[e + 2], s3 = g_esrc[e + 3];
        float n0 = g_dis[s0] * disd, n1 = g_dis[s1] * disd;
        float n2 = g_dis[s2] * disd, n3 = g_dis[s3] * disd;
        uint2 r0 = hv[(size_t)s0 * 32 + lane];
        uint2 r1 = hv[(size_t)s1 * 32 + lane];
        uint2 r2 = hv[(size_t)s2 * 32 + lane];
        uint2 r3 = hv[(size_t)s3 * 32 + lane];
        acc_h4(acc, r0, n0);
        acc_h4(acc, r1, n1);
        acc_h4(acc, r2, n2);
        acc_h4(acc, r3, n3);
    }
    for (; e < end; e++) {
        int s0 = g_esrc[e];
        acc_h4(acc, hv[(size_t)s0 * 32 + lane], g_dis[s0] * disd);
    }

    // evict-first store: agg is read exactly once (by the next GEMM)
    __stcs(((float4*)g_agg) + (size_t)node * 32 + lane, acc);
}

// ------- gather aggregation (F=64, fp16 h) + relu + log_softmax -------------
__global__ void k_aggregate64_softmax(const float* __restrict__ bias,
                                      float* __restrict__ out, int n) {
    int node = (int)(((size_t)blockIdx.x * blockDim.x + threadIdx.x) >> 5);
    int lane = threadIdx.x & 31;
    if (node >= n) return;

    const __half2* __restrict__ hv = (const __half2*)g_h;  // 32 half2 per row
    float disd = g_dis[node];

    float2 acc = ((const float2*)bias)[lane];
    {
        float2 v = __half22float2(hv[(size_t)node * 32 + lane]);
        float nrm = disd * disd;
        acc.x += v.x * nrm; acc.y += v.y * nrm;
    }

    int e = g_rowptr[node];
    int end = g_rowptr[node + 1];
    for (; e + 3 < end; e += 4) {
        int s0 = g_esrc[e],     s1 = g_esrc[e + 1];
        int s2 = g_esrc[e + 2], s3 = g_esrc[e + 3];
        float n0 = g_dis[s0] * disd, n1 = g_dis[s1] * disd;
        float n2 = g_dis[s2] * disd, n3 = g_dis[s3] * disd;
        float2 v0 = __half22float2(hv[(size_t)s0 * 32 + lane]);
        float2 v1 = __half22float2(hv[(size_t)s1 * 32 + lane]);
        float2 v2 = __half22float2(hv[(size_t)s2 * 32 + lane]);
        float2 v3 = __half22float2(hv[(size_t)s3 * 32 + lane]);
        acc.x += v0.x * n0 + v1.x * n1 + v2.x * n2 + v3.x * n3;
        acc.y += v0.y * n0 + v1.y * n1 + v2.y * n2 + v3.y * n3;
    }
    for (; e < end; e++) {
        int s0 = g_esrc[e];
        float n0 = g_dis[s0] * disd;
        float2 v0 = __half22float2(hv[(size_t)s0 * 32 + lane]);
        acc.x += v0.x * n0; acc.y += v0.y * n0;
    }

    acc.x = fmaxf(acc.x, 0.f);
    acc.y = fmaxf(acc.y, 0.f);

    float m = fmaxf(acc.x, acc.y);
#pragma unroll
    for (int off = 16; off; off >>= 1) m = fmaxf(m, __shfl_xor_sync(0xFFFFFFFFu, m, off));

    float ssum = expf(acc.x - m) + expf(acc.y - m);
#pragma unroll
    for (int off = 16; off; off >>= 1) ssum += __shfl_xor_sync(0xFFFFFFFFu, ssum, off);

    float l = logf(ssum);
    float2 o;
    o.x = acc.x - m - l;
    o.y = acc.y - m - l;
    __stcs(((float2*)out) + (size_t)node * 32 + lane, o);
}

// ----------------------------------------------------------------------------
extern "C" void kernel_launch(void* const* d_in, const int* in_sizes, int n_in,
                              void* d_out, int out_size) {
    const float* x  = (const float*)d_in[0];
    const int* ei   = (const int*)d_in[1];
    const float* W0 = (const float*)d_in[2];
    const float* b0 = (const float*)d_in[3];
    const float* W1 = (const float*)d_in[4];
    const float* b1 = (const float*)d_in[5];
    const float* W2 = (const float*)d_in[6];
    const float* b2 = (const float*)d_in[7];
    float* out = (float*)d_out;

    const int N = in_sizes[0] / 128;
    const int E = in_sizes[1] / 2;
    const int* src = ei;
    const int* dst = ei + E;

    const int T = 256;
    const int nb = (N + 1023) / 1024;

    // one-time side stream + events (created on the uncaptured correctness call)
    static cudaStream_t s_side = nullptr;
    static cudaEvent_t ev_fork = nullptr, ev_csr = nullptr;
    if (s_side == nullptr) {
        cudaStreamCreateWithFlags(&s_side, cudaStreamNonBlocking);
        cudaEventCreateWithFlags(&ev_fork, cudaEventDisableTiming);
        cudaEventCreateWithFlags(&ev_csr, cudaEventDisableTiming);
    }

    // ---- fork: CSR build on side stream, GEMM-0 on main stream
    cudaEventRecord(ev_fork, 0);
    cudaStreamWaitEvent(s_side, ev_fork, 0);

    k_deg_init<<<(N + T - 1) / T, T, 0, s_side>>>(N);
    k_deg_count<<<(E + T - 1) / T, T, 0, s_side>>>(dst, E);
    k_deg_rsqrt<<<(N + T - 1) / T, T, 0, s_side>>>(N);
    k_scan_local<<<nb, 1024, 0, s_side>>>(N);
    k_scan_bsums<<<1, 128, 0, s_side>>>(nb);
    k_scan_add<<<nb, 1024, 0, s_side>>>(N, nb);
    k_fill<<<(E + T - 1) / T, T, 0, s_side>>>(src, dst, E);
    cudaEventRecord(ev_csr, s_side);

    const int gemmBlocks = (N + 127) / 128;
    const int aggBlocks = (N * 32 + T - 1) / T;

    // ---- layer 0: 128 -> 128 (GEMM concurrent with CSR build)
    k_gemm<128, 8, false><<<gemmBlocks, 512>>>(x, W0, N);

    cudaStreamWaitEvent(0, ev_csr, 0);   // join: aggregation needs CSR + dis

    k_aggregate128<<<aggBlocks, T>>>(b0, N);

    // ---- layer 1: 128 -> 128 (relu fused into GEMM A load)
    k_gemm<128, 8, true><<<gemmBlocks, 512>>>(nullptr, W1, N);
    k_aggregate128<<<aggBlocks, T>>>(b1, N);

    // ---- layer 2: 128 -> 64, aggregation fused with relu + log_softmax
    k_gemm<64, 4, true><<<gemmBlocks, 512>>>(nullptr, W2, N);
    k_aggregate64_softmax<<<aggBlocks, T>>>(b2, out, N);
}